// round 6
// baseline (speedup 1.0000x reference)
#include <cuda_runtime.h>
#include <cstddef>

#define BSZ   256
#define NN    2048
#define KK    64
#define KP1   65
#define NT    256
#define RPT   8
#define NWARP 8
#define RSTR  132
#define MAXIT 200
#define EPS_F 0.1f
#define CONV_TOL 5e-5f
#define MU_F  (1.f/2048.f)

typedef unsigned long long u64;

__device__ unsigned g_maxEnc = 0u;
__device__ unsigned g_minEnc = 0xffffffffu;
__device__ int      g_anyMask = 0;
__device__ int      g_t1 = 0;
__device__ int      g_t2 = 0;
__device__ int      g_phase = 0;
__device__ float    g_alpha;
__device__ float    g_filled;
__device__ float    g_normPart[BSZ];

__device__ __forceinline__ u64 pack2(float lo, float hi){
  u64 r; asm("mov.b64 %0, {%1,%2};" : "=l"(r) : "f"(lo), "f"(hi)); return r;
}
__device__ __forceinline__ void unpack2(u64 v, float& lo, float& hi){
  asm("mov.b64 {%0,%1}, %2;" : "=f"(lo), "=f"(hi) : "l"(v));
}
__device__ __forceinline__ u64 fma2(u64 a, u64 b, u64 c){
  u64 d; asm("fma.rn.f32x2 %0, %1, %2, %3;" : "=l"(d) : "l"(a), "l"(b), "l"(c)); return d;
}
__device__ __forceinline__ u64 mul2(u64 a, u64 b){
  u64 d; asm("mul.rn.f32x2 %0, %1, %2;" : "=l"(d) : "l"(a), "l"(b)); return d;
}
__device__ __forceinline__ u64 add2(u64 a, u64 b){
  u64 d; asm("add.rn.f32x2 %0, %1, %2;" : "=l"(d) : "l"(a), "l"(b)); return d;
}
__device__ __forceinline__ float tanhA(float x){
  float r; asm("tanh.approx.f32 %0, %1;" : "=f"(r) : "f"(x)); return r;
}
__device__ __forceinline__ unsigned encF(float f){
  unsigned u = __float_as_uint(f);
  return (u & 0x80000000u) ? ~u : (u | 0x80000000u);
}
__device__ __forceinline__ float decF(unsigned e){
  unsigned u = (e & 0x80000000u) ? (e & 0x7fffffffu) : ~e;
  return __uint_as_float(u);
}

__global__ void __launch_bounds__(NT, 2) k_all(
    const float* __restrict__ scores,
    const float* __restrict__ W,
    float* __restrict__ out)
{
  __shared__ __align__(16) float sh_s[NN];
  __shared__ __align__(16) float sh_red[KP1*RSTR];
  __shared__ __align__(16) u64   sh_coefd[KP1+1];     // (c,c) duplicated pairs
  __shared__ u64   sh_cp[KK/2];
  __shared__ u64   sh_izp[KK/2];
  __shared__ float sh_tk[KK];
  __shared__ float sh_invZn[KK];
  __shared__ float sh_wred[NWARP];
  __shared__ float sh_par[2];
  __shared__ float sh_scalar[1];
  __shared__ unsigned sMx[NWARP], sMn[NWARP], sAn[NWARP];
  __shared__ int   sh_conv[2];
  __shared__ int   sh_last;

  const int tid  = threadIdx.x;
  const int wid  = tid >> 5;
  const int lane = tid & 31;
  const int b    = blockIdx.x;
  const float ninf = __int_as_float(0xff800000);
  const float* sc = scores + (size_t)b*NN;

  // ===== phase A: load + local min/max/any + global params via ticket/spin =====
  unsigned mx=0u, mn=0xffffffffu, any=0u;
  #pragma unroll
  for (int j=0;j<RPT;j++){
    int n = tid + j*NT;
    float x = sc[n];
    sh_s[n] = x;
    bool neg = (x==ninf);
    any |= (neg?1u:0u);
    unsigned e = encF(x);
    mx = max(mx,e);
    mn = min(mn, neg?0xffffffffu:e);
  }
  mx=__reduce_max_sync(0xffffffffu,mx);
  mn=__reduce_min_sync(0xffffffffu,mn);
  any=__reduce_or_sync(0xffffffffu,any);
  if (lane==0){ sMx[wid]=mx; sMn[wid]=mn; sAn[wid]=any; }
  __syncthreads();
  if (tid==0){
    #pragma unroll
    for (int q=1;q<NWARP;q++){ mx=max(mx,sMx[q]); mn=min(mn,sMn[q]); any|=sAn[q]; }
    atomicMax(&g_maxEnc,mx); atomicMin(&g_minEnc,mn);
    if (any) atomicOr(&g_anyMask,1);
    __threadfence();
    if (atomicAdd(&g_t1,1) == BSZ-1){
      unsigned MX=*(volatile unsigned*)&g_maxEnc;
      unsigned MN=*(volatile unsigned*)&g_minEnc;
      int AN=*(volatile int*)&g_anyMask;
      float maxS=decF(MX), minS=decF(MN);
      float filled = minS-(maxS-minS);
      float minF = AN ? fminf(filled,minS) : minS;
      float maxF = fmaxf(maxS,minF);
      float c1=minF*minF, c2=maxF*maxF;
      float c3=(minF-64.f)*(minF-64.f), c4=(maxF-64.f)*(maxF-64.f);
      float cmax=fmaxf(fmaxf(c1,c2),fmaxf(c3,c4));
      *(volatile float*)&g_alpha  = 1.f/(EPS_F*cmax);
      *(volatile float*)&g_filled = filled;
      __threadfence();
      *(volatile int*)&g_phase = 1;
    }
    while (*(volatile int*)&g_phase == 0) __nanosleep(64);
    __threadfence();
    sh_par[0]=*(volatile float*)&g_alpha;
    sh_par[1]=*(volatile float*)&g_filled;
  }
  __syncthreads();
  const float alpha  = sh_par[0];
  const float filled = sh_par[1];

  #pragma unroll
  for (int j=0;j<RPT;j++){
    int n = tid + j*NT;
    float x = sh_s[n];
    if (x == ninf) sh_s[n] = filled;
  }
  if (tid < KP1){
    float a = (float)tid;
    float c = __expf(-alpha*a*a) * (1.f/(float)KP1);
    sh_coefd[tid] = pack2(c,c);
  }
  if (tid == 0){ sh_conv[0]=0; sh_conv[1]=0; }
  __syncthreads();

  u64 w2[4];
  #pragma unroll
  for (int q=0;q<4;q++){
    float wa = __expf(2.f*alpha*sh_s[tid + (2*q  )*NT]);
    float wb = __expf(2.f*alpha*sh_s[tid + (2*q+1)*NT]);
    w2[q] = pack2(wa, wb);
  }

  // Steffensen state — owner thread of anchor a: wid*9 + lane == a, lane<9
  const int myA = wid*9 + lane;
  const bool owner = (lane < 9) && (myA <= KK);
  float h0=0.f, h1=0.f, oldc=0.f;
  if (owner){
    float a = (float)myA;
    float c = __expf(-alpha*a*a) * (1.f/(float)KP1);
    h0 = c; h1 = c; oldc = c;
  }
  u64 y2[4];

  // ===== Sinkhorn loop =====
  #pragma unroll 1
  for (int it=0; it<MAXIT; ++it){
    // u-update: acc = sum_a coef[a] w^a (Horner over duplicated-pair coefs)
    {
      u64 a0,a1,a2,a3;
      a0=a1=a2=a3=sh_coefd[KK];
      const ulonglong2* cf2 = (const ulonglong2*)sh_coefd;
      #pragma unroll
      for (int q2=31; q2>=0; --q2){
        ulonglong2 cc = cf2[q2];
        a0=fma2(a0,w2[0],cc.y); a1=fma2(a1,w2[1],cc.y); a2=fma2(a2,w2[2],cc.y); a3=fma2(a3,w2[3],cc.y);
        a0=fma2(a0,w2[0],cc.x); a1=fma2(a1,w2[1],cc.x); a2=fma2(a2,w2[2],cc.x); a3=fma2(a3,w2[3],cc.x);
      }
      float lo,hi;
      unpack2(a0,lo,hi); y2[0]=pack2(__fdividef(MU_F,lo), __fdividef(MU_F,hi));
      unpack2(a1,lo,hi); y2[1]=pack2(__fdividef(MU_F,lo), __fdividef(MU_F,hi));
      unpack2(a2,lo,hi); y2[2]=pack2(__fdividef(MU_F,lo), __fdividef(MU_F,hi));
      unpack2(a3,lo,hi); y2[3]=pack2(__fdividef(MU_F,lo), __fdividef(MU_F,hi));
    }
    // v-update power sums: per-anchor 16 partials/warp into sh_red
    {
      u64 t0=y2[0], t1=y2[1], t2=y2[2], t3=y2[3];
      #pragma unroll
      for (int a=0;a<KP1;a++){
        u64 p = add2(add2(t0,t1), add2(t2,t3));
        float lo,hi; unpack2(p,lo,hi);
        float mv = lo + hi;
        mv += __shfl_xor_sync(0xffffffffu, mv, 16);
        if (lane < 16) sh_red[a*RSTR + wid*16 + lane] = mv;
        if (a < KK){
          t0=mul2(t0,w2[0]); t1=mul2(t1,w2[1]); t2=mul2(t2,w2[2]); t3=mul2(t3,w2[3]);
        }
      }
    }
    __syncthreads();
    // parallel final reduce: warp w sums anchors 9w..9w+8 (128 partials each)
    {
      float myMM = 1.f;
      #pragma unroll
      for (int i=0;i<9;i++){
        int a = wid*9 + i;
        if (a <= KK){
          float4 v4 = *(const float4*)&sh_red[a*RSTR + 4*lane];
          float sum = (v4.x+v4.y)+(v4.z+v4.w);
          #pragma unroll
          for (int o=16;o>0;o>>=1) sum += __shfl_xor_sync(0xffffffffu, sum, o);
          if (lane == i) myMM = sum;
        }
      }
      if (owner){
        float nuv = (myA==0) ? ((float)(NN-KK)/(float)NN) : MU_F;
        float newc = __fdividef(nuv, myMM);
        if (fabsf(newc - oldc) > CONV_TOL*fabsf(oldc)) sh_conv[it&1] = 1;
        float store = newc;
        if ((it & 1) == 0){
          h1 = newc;                       // first plain step of the pair
        } else {                           // Steffensen extrapolation
          float d1 = h1 - h0, d2 = newc - h1;
          float den = d2 - d1;
          if (fabsf(den) > 1e-30f){
            float ext = newc - (d2*d2)/den;
            if (ext > 0.f && isfinite(ext)) store = ext;
          }
          h0 = store;                      // restart history
        }
        sh_coefd[myA] = pack2(store, store);
        oldc = store;
        if (myA == 0) sh_conv[(it+1)&1] = 0;
      }
    }
    __syncthreads();
    if (sh_conv[it&1] == 0) break;
  }

  // ===== hybrid bitonic sort: 8 consecutive elems per thread =====
  float sv[8];
  const int base8 = tid*8;
  {
    float4 p0 = *(const float4*)&sh_s[base8];
    float4 p1 = *(const float4*)&sh_s[base8+4];
    sv[0]=p0.x; sv[1]=p0.y; sv[2]=p0.z; sv[3]=p0.w;
    sv[4]=p1.x; sv[5]=p1.y; sv[6]=p1.z; sv[7]=p1.w;
  }
  for (int kk2=2; kk2<=NN; kk2<<=1){
    for (int jj=kk2>>1; jj>=256; jj>>=1){
      *(float4*)&sh_red[base8]   = make_float4(sv[0],sv[1],sv[2],sv[3]);
      *(float4*)&sh_red[base8+4] = make_float4(sv[4],sv[5],sv[6],sv[7]);
      __syncthreads();
      int delta = jj>>3;
      int pc = tid ^ delta;
      bool tmin = (((base8 & kk2)==0) == ((tid & delta)==0));
      float4 q0 = *(const float4*)&sh_red[pc*8];
      float4 q1 = *(const float4*)&sh_red[pc*8+4];
      float o[8] = {q0.x,q0.y,q0.z,q0.w,q1.x,q1.y,q1.z,q1.w};
      #pragma unroll
      for (int m=0;m<8;m++) sv[m] = tmin ? fminf(sv[m],o[m]) : fmaxf(sv[m],o[m]);
      __syncthreads();
    }
    {
      int jj0 = (kk2>>1) > 128 ? 128 : (kk2>>1);
      for (int jj=jj0; jj>=8; jj>>=1){
        int delta = jj>>3;
        bool tmin = (((base8 & kk2)==0) == ((tid & delta)==0));
        #pragma unroll
        for (int m=0;m<8;m++){
          float o = __shfl_xor_sync(0xffffffffu, sv[m], delta);
          sv[m] = tmin ? fminf(sv[m],o) : fmaxf(sv[m],o);
        }
      }
    }
    {
      int jj0 = (kk2>>1) > 4 ? 4 : (kk2>>1);
      for (int jj=jj0; jj>=1; jj>>=1){
        #pragma unroll
        for (int m=0;m<8;m++){
          if ((m & jj)==0){
            int m2 = m | jj;
            bool asc = (((base8+m) & kk2)==0);
            float a=sv[m], bb=sv[m2];
            if ((a>bb)==asc){ sv[m]=bb; sv[m2]=a; }
          }
        }
      }
    }
  }

  // ===== tau + top-K =====
  {
    float4 w0 = *(const float4*)&W[base8];
    float4 w1 = *(const float4*)&W[base8+4];
    float part = sv[0]*w0.x + sv[1]*w0.y + sv[2]*w0.z + sv[3]*w0.w
               + sv[4]*w1.x + sv[5]*w1.y + sv[6]*w1.z + sv[7]*w1.w;
    #pragma unroll
    for (int o=16;o>0;o>>=1) part += __shfl_xor_sync(0xffffffffu, part, o);
    if (lane==0) sh_wred[wid] = part;
    if (tid >= NT-8){
      #pragma unroll
      for (int m=0;m<8;m++) sh_tk[NN-1-base8-m] = sv[m];
    }
    __syncthreads();
    if (tid==0){
      float tau=0.f;
      #pragma unroll
      for (int q=0;q<NWARP;q++) tau += sh_wred[q];
      sh_scalar[0] = 0.5f/tau;
    }
    __syncthreads();
  }
  const float hTau = sh_scalar[0];

  // ===== Gamma0 column sums Z_k =====
  #pragma unroll 1
  for (int c=0;c<4;c++){
    float z[16];
    #pragma unroll
    for (int q=0;q<16;q++) z[q]=0.f;
    #pragma unroll
    for (int j=0;j<RPT;j++){
      float s = sh_s[tid+j*NT];
      #pragma unroll
      for (int q=0;q<16;q++){
        float d = fabsf(sh_tk[c*16+q]-s);
        z[q] += fmaf(-0.5f, tanhA(d*hTau), 0.5f);
      }
    }
    #pragma unroll
    for (int q=0;q<16;q++){
      float mv = z[q];
      #pragma unroll
      for (int o=16;o>0;o>>=1) mv += __shfl_xor_sync(0xffffffffu, mv, o);
      if (lane==0) sh_red[q*NWARP + wid] = mv;
    }
    __syncthreads();
    if (tid < 16){
      float Z=0.f;
      #pragma unroll
      for (int q=0;q<NWARP;q++) Z += sh_red[tid*NWARP+q];
      sh_invZn[c*16+tid] = __fdividef(1.f, Z*(float)NN);
    }
    __syncthreads();
  }

  // packed per-pair tables: pair i covers anchors (lo=2i+2 -> k=62-2i, hi=2i+1 -> k=63-2i)
  if (tid < KK/2){
    const float* cf = (const float*)sh_coefd;   // low float of each pair, stride 2
    sh_cp [tid] = pack2(cf[2*(2*tid+2)], cf[2*(2*tid+1)]);
    sh_izp[tid] = pack2(sh_invZn[62-2*tid], sh_invZn[63-2*tid]);
  }
  __syncthreads();

  // ===== final: Gamma, A, ||Gamma-Gamma0||^2 (paired f32x2) =====
  const u64 NN2 = pack2(2048.f, 2048.f);
  const u64 MH2 = pack2(-0.5f, -0.5f);
  const u64 PH2 = pack2( 0.5f,  0.5f);
  const u64 M12 = pack2(-1.f, -1.f);
  const float coef0 = ((const float*)sh_coefd)[0];
  float nrm = 0.f;
  u64 nrm2 = pack2(0.f, 0.f);
  #pragma unroll 1
  for (int j=0;j<RPT;j++){
    int n = tid + j*NT;
    float s = sh_s[n];
    float yj, wj;
    { float lo,hi;
      unpack2(y2[j>>1], lo, hi); yj = (j&1)?hi:lo;
      unpack2(w2[j>>1], lo, hi); wj = (j&1)?hi:lo; }
    float* orow = out + ((size_t)b*NN + n)*KK;
    float gam64 = yj * coef0;
    float ww = wj*wj;
    u64 ww2 = pack2(ww, ww);
    float t1v = yj*wj;
    u64 G2 = pack2(t1v*wj, t1v);
    u64 rs2 = pack2(0.f, 0.f);
    #pragma unroll 4
    for (int g=0; g<16; ++g){
      int kb = 60 - 4*g;
      u64 gamP = mul2(G2, sh_cp[2*g]);   G2 = mul2(G2, ww2);
      u64 gamQ = mul2(G2, sh_cp[2*g+1]); G2 = mul2(G2, ww2);
      float thP0 = tanhA(fabsf(sh_tk[kb+2]-s)*hTau);
      float thP1 = tanhA(fabsf(sh_tk[kb+3]-s)*hTau);
      float thQ0 = tanhA(fabsf(sh_tk[kb  ]-s)*hTau);
      float thQ1 = tanhA(fabsf(sh_tk[kb+1]-s)*hTau);
      u64 sgP = fma2(pack2(thP0,thP1), MH2, PH2);
      u64 sgQ = fma2(pack2(thQ0,thQ1), MH2, PH2);
      u64 g0P = mul2(sgP, sh_izp[2*g]);
      u64 g0Q = mul2(sgQ, sh_izp[2*g+1]);
      rs2 = add2(rs2, add2(g0P, g0Q));
      u64 dP = fma2(g0P, M12, gamP);
      u64 dQ = fma2(g0Q, M12, gamQ);
      nrm2 = fma2(dP, dP, nrm2);
      nrm2 = fma2(dQ, dQ, nrm2);
      float ql,qh,pl,ph;
      unpack2(mul2(gamQ, NN2), ql, qh);
      unpack2(mul2(gamP, NN2), pl, ph);
      *(float4*)(orow + kb) = make_float4(ql, qh, pl, ph);
    }
    float rl,rh; unpack2(rs2, rl, rh);
    float last = MU_F - (rl + rh);
    last = fminf(fmaxf(last, 1e-20f), 1.f-1e-20f);
    float dl = gam64 - last;
    nrm = fmaf(dl, dl, nrm);
  }
  { float nl,nh; unpack2(nrm2, nl, nh); nrm += nl + nh; }
  #pragma unroll
  for (int o=16;o>0;o>>=1) nrm += __shfl_xor_sync(0xffffffffu, nrm, o);
  if (lane==0) sh_wred[wid] = nrm;
  __syncthreads();
  if (tid==0){
    float sA=0.f;
    #pragma unroll
    for (int q=0;q<NWARP;q++) sA += sh_wred[q];
    g_normPart[b] = sA;
  }

  // ===== final norm via last-CTA ticket (self-resetting globals) =====
  if (tid==0){
    __threadfence();
    sh_last = (atomicAdd(&g_t2,1) == BSZ-1) ? 1 : 0;
  }
  __syncthreads();
  if (sh_last){
    __threadfence();
    float v = *(volatile float*)&g_normPart[tid];
    #pragma unroll
    for (int o=16;o>0;o>>=1) v += __shfl_xor_sync(0xffffffffu, v, o);
    if (lane==0) sh_wred[wid] = v;
    __syncthreads();
    if (tid==0){
      float sT=0.f;
      #pragma unroll
      for (int q=0;q<NWARP;q++) sT += sh_wred[q];
      out[(size_t)BSZ*NN*KK] = sqrtf(sT);
      g_t1=0; g_t2=0;
      g_maxEnc=0u; g_minEnc=0xffffffffu; g_anyMask=0;
      __threadfence();
      *(volatile int*)&g_phase = 0;
    }
  }
}

extern "C" void kernel_launch(void* const* d_in, const int* in_sizes, int n_in,
                              void* d_out, int out_size)
{
  const float* scores = (const float*)d_in[0];
  const float* W      = (const float*)d_in[1];
  if (n_in >= 2 && in_sizes[0] == NN && in_sizes[1] == BSZ*NN){
    const float* tmp = scores; scores = W; W = tmp;
  }
  float* out = (float*)d_out;
  (void)out_size;

  k_all<<<BSZ, NT>>>(scores, W, out);
}

// round 10
// speedup vs baseline: 1.0234x; 1.0234x over previous
#include <cuda_runtime.h>
#include <cstddef>

#define BSZ   256
#define NN    2048
#define KK    64
#define KP1   65
#define NT    256
#define RPT   8
#define NWARP 8
#define RSTR  132
#define MAXIT 200
#define EPS_F 0.1f
#define CONV_TOL 2e-4f
#define MU_F  (1.f/2048.f)

typedef unsigned long long u64;

__device__ unsigned g_maxEnc = 0u;
__device__ unsigned g_minEnc = 0xffffffffu;
__device__ int      g_anyMask = 0;
__device__ int      g_t1 = 0;
__device__ int      g_t2 = 0;
__device__ int      g_phase = 0;
__device__ float    g_alpha;
__device__ float    g_filled;
__device__ float    g_normPart[BSZ];

__device__ __forceinline__ u64 pack2(float lo, float hi){
  u64 r; asm("mov.b64 %0, {%1,%2};" : "=l"(r) : "f"(lo), "f"(hi)); return r;
}
__device__ __forceinline__ void unpack2(u64 v, float& lo, float& hi){
  asm("mov.b64 {%0,%1}, %2;" : "=f"(lo), "=f"(hi) : "l"(v));
}
__device__ __forceinline__ u64 fma2(u64 a, u64 b, u64 c){
  u64 d; asm("fma.rn.f32x2 %0, %1, %2, %3;" : "=l"(d) : "l"(a), "l"(b), "l"(c)); return d;
}
__device__ __forceinline__ u64 mul2(u64 a, u64 b){
  u64 d; asm("mul.rn.f32x2 %0, %1, %2;" : "=l"(d) : "l"(a), "l"(b)); return d;
}
__device__ __forceinline__ u64 add2(u64 a, u64 b){
  u64 d; asm("add.rn.f32x2 %0, %1, %2;" : "=l"(d) : "l"(a), "l"(b)); return d;
}
__device__ __forceinline__ float tanhA(float x){
  float r; asm("tanh.approx.f32 %0, %1;" : "=f"(r) : "f"(x)); return r;
}
__device__ __forceinline__ unsigned encF(float f){
  unsigned u = __float_as_uint(f);
  return (u & 0x80000000u) ? ~u : (u | 0x80000000u);
}
__device__ __forceinline__ float decF(unsigned e){
  unsigned u = (e & 0x80000000u) ? (e & 0x7fffffffu) : ~e;
  return __uint_as_float(u);
}

__global__ void __launch_bounds__(NT, 2) k_all(
    const float* __restrict__ scores,
    const float* __restrict__ W,
    float* __restrict__ out)
{
  __shared__ __align__(16) float sh_s[NN];
  __shared__ __align__(16) float sh_red[KP1*RSTR];
  __shared__ __align__(16) u64   sh_coefd[KP1+1];     // (c,c) duplicated pairs
  __shared__ u64   sh_cp[KK/2];
  __shared__ u64   sh_izp[KK/2];
  __shared__ float sh_tk[KK];
  __shared__ float sh_invZn[KK];
  __shared__ float sh_wred[NWARP];
  __shared__ float sh_par[2];
  __shared__ float sh_scalar[1];
  __shared__ unsigned sMx[NWARP], sMn[NWARP], sAn[NWARP];
  __shared__ int   sh_conv[2];
  __shared__ int   sh_last;

  const int tid  = threadIdx.x;
  const int wid  = tid >> 5;
  const int lane = tid & 31;
  const int b    = blockIdx.x;
  const float ninf = __int_as_float(0xff800000);
  const float* sc = scores + (size_t)b*NN;

  // ===== phase A: load + local min/max/any + global params via ticket/spin =====
  unsigned mx=0u, mn=0xffffffffu, any=0u;
  #pragma unroll
  for (int j=0;j<RPT;j++){
    int n = tid + j*NT;
    float x = sc[n];
    sh_s[n] = x;
    bool neg = (x==ninf);
    any |= (neg?1u:0u);
    unsigned e = encF(x);
    mx = max(mx,e);
    mn = min(mn, neg?0xffffffffu:e);
  }
  mx=__reduce_max_sync(0xffffffffu,mx);
  mn=__reduce_min_sync(0xffffffffu,mn);
  any=__reduce_or_sync(0xffffffffu,any);
  if (lane==0){ sMx[wid]=mx; sMn[wid]=mn; sAn[wid]=any; }
  __syncthreads();
  if (tid==0){
    #pragma unroll
    for (int q=1;q<NWARP;q++){ mx=max(mx,sMx[q]); mn=min(mn,sMn[q]); any|=sAn[q]; }
    atomicMax(&g_maxEnc,mx); atomicMin(&g_minEnc,mn);
    if (any) atomicOr(&g_anyMask,1);
    __threadfence();
    if (atomicAdd(&g_t1,1) == BSZ-1){
      unsigned MX=*(volatile unsigned*)&g_maxEnc;
      unsigned MN=*(volatile unsigned*)&g_minEnc;
      int AN=*(volatile int*)&g_anyMask;
      float maxS=decF(MX), minS=decF(MN);
      float filled = minS-(maxS-minS);
      float minF = AN ? fminf(filled,minS) : minS;
      float maxF = fmaxf(maxS,minF);
      float c1=minF*minF, c2=maxF*maxF;
      float c3=(minF-64.f)*(minF-64.f), c4=(maxF-64.f)*(maxF-64.f);
      float cmax=fmaxf(fmaxf(c1,c2),fmaxf(c3,c4));
      *(volatile float*)&g_alpha  = 1.f/(EPS_F*cmax);
      *(volatile float*)&g_filled = filled;
      __threadfence();
      *(volatile int*)&g_phase = 1;
    }
    while (*(volatile int*)&g_phase == 0) __nanosleep(64);
    __threadfence();
    sh_par[0]=*(volatile float*)&g_alpha;
    sh_par[1]=*(volatile float*)&g_filled;
  }
  __syncthreads();
  const float alpha  = sh_par[0];
  const float filled = sh_par[1];

  #pragma unroll
  for (int j=0;j<RPT;j++){
    int n = tid + j*NT;
    float x = sh_s[n];
    if (x == ninf) sh_s[n] = filled;
  }
  if (tid < KP1){
    float a = (float)tid;
    float c = __expf(-alpha*a*a) * (1.f/(float)KP1);
    sh_coefd[tid] = pack2(c,c);
  }
  if (tid == 0){ sh_conv[0]=0; sh_conv[1]=0; }
  __syncthreads();

  u64 w2[4];
  #pragma unroll
  for (int q=0;q<4;q++){
    float wa = __expf(2.f*alpha*sh_s[tid + (2*q  )*NT]);
    float wb = __expf(2.f*alpha*sh_s[tid + (2*q+1)*NT]);
    w2[q] = pack2(wa, wb);
  }

  // Steffensen state (owner thread: tid == anchor a, tid < 65)
  float h0=0.f, h1=0.f, oldc=0.f;
  if (tid < KP1){
    float a = (float)tid;
    float c = __expf(-alpha*a*a) * (1.f/(float)KP1);
    h0 = c; h1 = c; oldc = c;
  }
  u64 y2[4];

  // ===== Sinkhorn loop =====
  #pragma unroll 1
  for (int it=0; it<MAXIT; ++it){
    // u-update: acc = sum_a coef[a] w^a (Horner over duplicated-pair coefs)
    {
      u64 a0,a1,a2,a3;
      a0=a1=a2=a3=sh_coefd[KK];
      const ulonglong2* cf2 = (const ulonglong2*)sh_coefd;
      #pragma unroll
      for (int q2=31; q2>=0; --q2){
        ulonglong2 cc = cf2[q2];
        a0=fma2(a0,w2[0],cc.y); a1=fma2(a1,w2[1],cc.y); a2=fma2(a2,w2[2],cc.y); a3=fma2(a3,w2[3],cc.y);
        a0=fma2(a0,w2[0],cc.x); a1=fma2(a1,w2[1],cc.x); a2=fma2(a2,w2[2],cc.x); a3=fma2(a3,w2[3],cc.x);
      }
      float lo,hi;
      unpack2(a0,lo,hi); y2[0]=pack2(__fdividef(MU_F,lo), __fdividef(MU_F,hi));
      unpack2(a1,lo,hi); y2[1]=pack2(__fdividef(MU_F,lo), __fdividef(MU_F,hi));
      unpack2(a2,lo,hi); y2[2]=pack2(__fdividef(MU_F,lo), __fdividef(MU_F,hi));
      unpack2(a3,lo,hi); y2[3]=pack2(__fdividef(MU_F,lo), __fdividef(MU_F,hi));
    }
    // v-update power sums: per-anchor 16 partials/warp into sh_red
    {
      u64 t0=y2[0], t1=y2[1], t2=y2[2], t3=y2[3];
      #pragma unroll
      for (int a=0;a<KP1;a++){
        u64 p = add2(add2(t0,t1), add2(t2,t3));
        float lo,hi; unpack2(p,lo,hi);
        float mv = lo + hi;
        mv += __shfl_xor_sync(0xffffffffu, mv, 16);
        if (lane < 16) sh_red[a*RSTR + wid*16 + lane] = mv;
        if (a < KK){
          t0=mul2(t0,w2[0]); t1=mul2(t1,w2[1]); t2=mul2(t2,w2[2]); t3=mul2(t3,w2[3]);
        }
      }
    }
    __syncthreads();
    // serial-owner final reduce: thread a sums its 128 partials (warps 0-2 only)
    if (tid < KP1){
      const float* row = &sh_red[tid*RSTR];
      float s0=0.f,s1=0.f,s2=0.f,s3=0.f;
      #pragma unroll
      for (int p=0;p<128;p+=4){ s0+=row[p]; s1+=row[p+1]; s2+=row[p+2]; s3+=row[p+3]; }
      float mm = (s0+s1)+(s2+s3);
      float nuv = (tid==0) ? ((float)(NN-KK)/(float)NN) : MU_F;
      float newc = __fdividef(nuv, mm);
      if (fabsf(newc - oldc) > CONV_TOL*fabsf(oldc)) sh_conv[it&1] = 1;
      float store = newc;
      if ((it & 1) == 0){
        h1 = newc;                         // first plain step of the pair
      } else {                             // Steffensen extrapolation
        float d1 = h1 - h0, d2 = newc - h1;
        float den = d2 - d1;
        if (fabsf(den) > 1e-30f){
          float ext = newc - (d2*d2)/den;
          if (ext > 0.f && isfinite(ext)) store = ext;
        }
        h0 = store;                        // restart history
      }
      sh_coefd[tid] = pack2(store, store);
      oldc = store;
      if (tid == 0) sh_conv[(it+1)&1] = 0;
    }
    __syncthreads();
    if (sh_conv[it&1] == 0) break;
  }

  // ===== hybrid bitonic sort: 8 consecutive elems per thread =====
  float sv[8];
  const int base8 = tid*8;
  {
    float4 p0 = *(const float4*)&sh_s[base8];
    float4 p1 = *(const float4*)&sh_s[base8+4];
    sv[0]=p0.x; sv[1]=p0.y; sv[2]=p0.z; sv[3]=p0.w;
    sv[4]=p1.x; sv[5]=p1.y; sv[6]=p1.z; sv[7]=p1.w;
  }
  for (int kk2=2; kk2<=NN; kk2<<=1){
    for (int jj=kk2>>1; jj>=256; jj>>=1){
      *(float4*)&sh_red[base8]   = make_float4(sv[0],sv[1],sv[2],sv[3]);
      *(float4*)&sh_red[base8+4] = make_float4(sv[4],sv[5],sv[6],sv[7]);
      __syncthreads();
      int delta = jj>>3;
      int pc = tid ^ delta;
      bool tmin = (((base8 & kk2)==0) == ((tid & delta)==0));
      float4 q0 = *(const float4*)&sh_red[pc*8];
      float4 q1 = *(const float4*)&sh_red[pc*8+4];
      float o[8] = {q0.x,q0.y,q0.z,q0.w,q1.x,q1.y,q1.z,q1.w};
      #pragma unroll
      for (int m=0;m<8;m++) sv[m] = tmin ? fminf(sv[m],o[m]) : fmaxf(sv[m],o[m]);
      __syncthreads();
    }
    {
      int jj0 = (kk2>>1) > 128 ? 128 : (kk2>>1);
      for (int jj=jj0; jj>=8; jj>>=1){
        int delta = jj>>3;
        bool tmin = (((base8 & kk2)==0) == ((tid & delta)==0));
        #pragma unroll
        for (int m=0;m<8;m++){
          float o = __shfl_xor_sync(0xffffffffu, sv[m], delta);
          sv[m] = tmin ? fminf(sv[m],o) : fmaxf(sv[m],o);
        }
      }
    }
    {
      int jj0 = (kk2>>1) > 4 ? 4 : (kk2>>1);
      for (int jj=jj0; jj>=1; jj>>=1){
        #pragma unroll
        for (int m=0;m<8;m++){
          if ((m & jj)==0){
            int m2 = m | jj;
            bool asc = (((base8+m) & kk2)==0);
            float a=sv[m], bb=sv[m2];
            if ((a>bb)==asc){ sv[m]=bb; sv[m2]=a; }
          }
        }
      }
    }
  }

  // ===== tau + top-K =====
  {
    float4 w0 = *(const float4*)&W[base8];
    float4 w1 = *(const float4*)&W[base8+4];
    float part = sv[0]*w0.x + sv[1]*w0.y + sv[2]*w0.z + sv[3]*w0.w
               + sv[4]*w1.x + sv[5]*w1.y + sv[6]*w1.z + sv[7]*w1.w;
    #pragma unroll
    for (int o=16;o>0;o>>=1) part += __shfl_xor_sync(0xffffffffu, part, o);
    if (lane==0) sh_wred[wid] = part;
    if (tid >= NT-8){
      #pragma unroll
      for (int m=0;m<8;m++) sh_tk[NN-1-base8-m] = sv[m];
    }
    __syncthreads();
    if (tid==0){
      float tau=0.f;
      #pragma unroll
      for (int q=0;q<NWARP;q++) tau += sh_wred[q];
      sh_scalar[0] = 0.5f/tau;
    }
    __syncthreads();
  }
  const float hTau = sh_scalar[0];

  // ===== Gamma0 column sums Z_k =====
  #pragma unroll 1
  for (int c=0;c<4;c++){
    float z[16];
    #pragma unroll
    for (int q=0;q<16;q++) z[q]=0.f;
    #pragma unroll
    for (int j=0;j<RPT;j++){
      float s = sh_s[tid+j*NT];
      #pragma unroll
      for (int q=0;q<16;q++){
        float d = fabsf(sh_tk[c*16+q]-s);
        z[q] += fmaf(-0.5f, tanhA(d*hTau), 0.5f);
      }
    }
    #pragma unroll
    for (int q=0;q<16;q++){
      float mv = z[q];
      #pragma unroll
      for (int o=16;o>0;o>>=1) mv += __shfl_xor_sync(0xffffffffu, mv, o);
      if (lane==0) sh_red[q*NWARP + wid] = mv;
    }
    __syncthreads();
    if (tid < 16){
      float Z=0.f;
      #pragma unroll
      for (int q=0;q<NWARP;q++) Z += sh_red[tid*NWARP+q];
      sh_invZn[c*16+tid] = __fdividef(1.f, Z*(float)NN);
    }
    __syncthreads();
  }

  // packed per-pair tables: pair i covers anchors (lo=2i+2 -> k=62-2i, hi=2i+1 -> k=63-2i)
  if (tid < KK/2){
    const float* cf = (const float*)sh_coefd;   // low float of each pair, stride 2
    sh_cp [tid] = pack2(cf[2*(2*tid+2)], cf[2*(2*tid+1)]);
    sh_izp[tid] = pack2(sh_invZn[62-2*tid], sh_invZn[63-2*tid]);
  }
  __syncthreads();

  // ===== final: Gamma, A, ||Gamma-Gamma0||^2 (paired f32x2) =====
  const u64 NN2 = pack2(2048.f, 2048.f);
  const u64 MH2 = pack2(-0.5f, -0.5f);
  const u64 PH2 = pack2( 0.5f,  0.5f);
  const u64 M12 = pack2(-1.f, -1.f);
  const float coef0 = ((const float*)sh_coefd)[0];
  float nrm = 0.f;
  u64 nrm2 = pack2(0.f, 0.f);
  #pragma unroll 1
  for (int j=0;j<RPT;j++){
    int n = tid + j*NT;
    float s = sh_s[n];
    float yj, wj;
    { float lo,hi;
      unpack2(y2[j>>1], lo, hi); yj = (j&1)?hi:lo;
      unpack2(w2[j>>1], lo, hi); wj = (j&1)?hi:lo; }
    float* orow = out + ((size_t)b*NN + n)*KK;
    float gam64 = yj * coef0;
    float ww = wj*wj;
    u64 ww2 = pack2(ww, ww);
    float t1v = yj*wj;
    u64 G2 = pack2(t1v*wj, t1v);
    u64 rs2 = pack2(0.f, 0.f);
    #pragma unroll 4
    for (int g=0; g<16; ++g){
      int kb = 60 - 4*g;
      u64 gamP = mul2(G2, sh_cp[2*g]);   G2 = mul2(G2, ww2);
      u64 gamQ = mul2(G2, sh_cp[2*g+1]); G2 = mul2(G2, ww2);
      float thP0 = tanhA(fabsf(sh_tk[kb+2]-s)*hTau);
      float thP1 = tanhA(fabsf(sh_tk[kb+3]-s)*hTau);
      float thQ0 = tanhA(fabsf(sh_tk[kb  ]-s)*hTau);
      float thQ1 = tanhA(fabsf(sh_tk[kb+1]-s)*hTau);
      u64 sgP = fma2(pack2(thP0,thP1), MH2, PH2);
      u64 sgQ = fma2(pack2(thQ0,thQ1), MH2, PH2);
      u64 g0P = mul2(sgP, sh_izp[2*g]);
      u64 g0Q = mul2(sgQ, sh_izp[2*g+1]);
      rs2 = add2(rs2, add2(g0P, g0Q));
      u64 dP = fma2(g0P, M12, gamP);
      u64 dQ = fma2(g0Q, M12, gamQ);
      nrm2 = fma2(dP, dP, nrm2);
      nrm2 = fma2(dQ, dQ, nrm2);
      float ql,qh,pl,ph;
      unpack2(mul2(gamQ, NN2), ql, qh);
      unpack2(mul2(gamP, NN2), pl, ph);
      *(float4*)(orow + kb) = make_float4(ql, qh, pl, ph);
    }
    float rl,rh; unpack2(rs2, rl, rh);
    float last = MU_F - (rl + rh);
    last = fminf(fmaxf(last, 1e-20f), 1.f-1e-20f);
    float dl = gam64 - last;
    nrm = fmaf(dl, dl, nrm);
  }
  { float nl,nh; unpack2(nrm2, nl, nh); nrm += nl + nh; }
  #pragma unroll
  for (int o=16;o>0;o>>=1) nrm += __shfl_xor_sync(0xffffffffu, nrm, o);
  if (lane==0) sh_wred[wid] = nrm;
  __syncthreads();
  if (tid==0){
    float sA=0.f;
    #pragma unroll
    for (int q=0;q<NWARP;q++) sA += sh_wred[q];
    g_normPart[b] = sA;
  }

  // ===== final norm via last-CTA ticket (self-resetting globals) =====
  if (tid==0){
    __threadfence();
    sh_last = (atomicAdd(&g_t2,1) == BSZ-1) ? 1 : 0;
  }
  __syncthreads();
  if (sh_last){
    __threadfence();
    float v = *(volatile float*)&g_normPart[tid];
    #pragma unroll
    for (int o=16;o>0;o>>=1) v += __shfl_xor_sync(0xffffffffu, v, o);
    if (lane==0) sh_wred[wid] = v;
    __syncthreads();
    if (tid==0){
      float sT=0.f;
      #pragma unroll
      for (int q=0;q<NWARP;q++) sT += sh_wred[q];
      out[(size_t)BSZ*NN*KK] = sqrtf(sT);
      g_t1=0; g_t2=0;
      g_maxEnc=0u; g_minEnc=0xffffffffu; g_anyMask=0;
      __threadfence();
      *(volatile int*)&g_phase = 0;
    }
  }
}

extern "C" void kernel_launch(void* const* d_in, const int* in_sizes, int n_in,
                              void* d_out, int out_size)
{
  const float* scores = (const float*)d_in[0];
  const float* W      = (const float*)d_in[1];
  if (n_in >= 2 && in_sizes[0] == NN && in_sizes[1] == BSZ*NN){
    const float* tmp = scores; scores = W; W = tmp;
  }
  float* out = (float*)d_out;
  (void)out_size;

  k_all<<<BSZ, NT>>>(scores, W, out);
}

// round 12
// speedup vs baseline: 1.1005x; 1.0754x over previous
#include <cuda_runtime.h>
#include <cstddef>

#define BSZ   256
#define NN    2048
#define KK    64
#define KP1   65
#define NT    256
#define RPT   8
#define NWARP 8
#define DD    14          // Taylor degree
#define QRS   16          // Qr row stride
#define QCS   66          // Qc row stride
#define TSTR  68          // T-partial row stride
#define MAXIT 200
#define EPS_F 0.1f
#define CONV_TOL 2e-4f
#define MU_F  (1.f/2048.f)

typedef unsigned long long u64;

__device__ unsigned g_maxEnc = 0u;
__device__ unsigned g_minEnc = 0xffffffffu;
__device__ int      g_anyMask = 0;
__device__ int      g_t1 = 0;
__device__ int      g_t2 = 0;
__device__ int      g_phase = 0;
__device__ float    g_alpha;
__device__ float    g_filled;
__device__ float    g_sbar;
__device__ float    g_normPart[BSZ];

__device__ __forceinline__ u64 pack2(float lo, float hi){
  u64 r; asm("mov.b64 %0, {%1,%2};" : "=l"(r) : "f"(lo), "f"(hi)); return r;
}
__device__ __forceinline__ void unpack2(u64 v, float& lo, float& hi){
  asm("mov.b64 {%0,%1}, %2;" : "=f"(lo), "=f"(hi) : "l"(v));
}
__device__ __forceinline__ u64 fma2(u64 a, u64 b, u64 c){
  u64 d; asm("fma.rn.f32x2 %0, %1, %2, %3;" : "=l"(d) : "l"(a), "l"(b), "l"(c)); return d;
}
__device__ __forceinline__ u64 mul2(u64 a, u64 b){
  u64 d; asm("mul.rn.f32x2 %0, %1, %2;" : "=l"(d) : "l"(a), "l"(b)); return d;
}
__device__ __forceinline__ u64 add2(u64 a, u64 b){
  u64 d; asm("add.rn.f32x2 %0, %1, %2;" : "=l"(d) : "l"(a), "l"(b)); return d;
}
__device__ __forceinline__ float tanhA(float x){
  float r; asm("tanh.approx.f32 %0, %1;" : "=f"(r) : "f"(x)); return r;
}
__device__ __forceinline__ unsigned encF(float f){
  unsigned u = __float_as_uint(f);
  return (u & 0x80000000u) ? ~u : (u | 0x80000000u);
}
__device__ __forceinline__ float decF(unsigned e){
  unsigned u = (e & 0x80000000u) ? (e & 0x7fffffffu) : ~e;
  return __uint_as_float(u);
}

__global__ void __launch_bounds__(NT, 2) k_all(
    const float* __restrict__ scores,
    const float* __restrict__ W,
    float* __restrict__ out)
{
  __shared__ __align__(16) float sh_s[NN];
  __shared__ __align__(16) float sh_red[NN+64];     // T-partials (DD*TSTR<2048) / sort buffer
  __shared__ __align__(16) float sh_Qc[DD*QCS];     // Qc[d][a] = lam_a^d/d!
  __shared__ __align__(16) float sh_Qr[KP1*QRS];    // Qr[a][d]
  __shared__ float sh_chi[KP1];
  __shared__ float sh_C[DD];
  __shared__ float sh_T[DD];
  __shared__ u64   sh_cp[KK/2];
  __shared__ u64   sh_izp[KK/2];
  __shared__ float sh_tk[KK];
  __shared__ float sh_invZn[KK];
  __shared__ float sh_wred[NWARP];
  __shared__ float sh_par[3];
  __shared__ float sh_scalar[1];
  __shared__ unsigned sMx[NWARP], sMn[NWARP], sAn[NWARP];
  __shared__ int   sh_conv[2];
  __shared__ int   sh_last;

  const int tid  = threadIdx.x;
  const int wid  = tid >> 5;
  const int lane = tid & 31;
  const int b    = blockIdx.x;
  const float ninf = __int_as_float(0xff800000);
  const float* sc = scores + (size_t)b*NN;

  // ===== phase A: load + local min/max/any + global params via ticket/spin =====
  unsigned mx=0u, mn=0xffffffffu, any=0u;
  #pragma unroll
  for (int j=0;j<RPT;j++){
    int n = tid + j*NT;
    float x = sc[n];
    sh_s[n] = x;
    bool neg = (x==ninf);
    any |= (neg?1u:0u);
    unsigned e = encF(x);
    mx = max(mx,e);
    mn = min(mn, neg?0xffffffffu:e);
  }
  mx=__reduce_max_sync(0xffffffffu,mx);
  mn=__reduce_min_sync(0xffffffffu,mn);
  any=__reduce_or_sync(0xffffffffu,any);
  if (lane==0){ sMx[wid]=mx; sMn[wid]=mn; sAn[wid]=any; }
  __syncthreads();
  if (tid==0){
    #pragma unroll
    for (int q=1;q<NWARP;q++){ mx=max(mx,sMx[q]); mn=min(mn,sMn[q]); any|=sAn[q]; }
    atomicMax(&g_maxEnc,mx); atomicMin(&g_minEnc,mn);
    if (any) atomicOr(&g_anyMask,1);
    __threadfence();
    if (atomicAdd(&g_t1,1) == BSZ-1){
      unsigned MX=*(volatile unsigned*)&g_maxEnc;
      unsigned MN=*(volatile unsigned*)&g_minEnc;
      int AN=*(volatile int*)&g_anyMask;
      float maxS=decF(MX), minS=decF(MN);
      float filled = minS-(maxS-minS);
      float minF = AN ? fminf(filled,minS) : minS;
      float maxF = fmaxf(maxS,minF);
      float c1=minF*minF, c2=maxF*maxF;
      float c3=(minF-64.f)*(minF-64.f), c4=(maxF-64.f)*(maxF-64.f);
      float cmax=fmaxf(fmaxf(c1,c2),fmaxf(c3,c4));
      *(volatile float*)&g_alpha  = 1.f/(EPS_F*cmax);
      *(volatile float*)&g_filled = filled;
      *(volatile float*)&g_sbar   = 0.5f*(minF+maxF);
      __threadfence();
      *(volatile int*)&g_phase = 1;
    }
    while (*(volatile int*)&g_phase == 0) __nanosleep(64);
    __threadfence();
    sh_par[0]=*(volatile float*)&g_alpha;
    sh_par[1]=*(volatile float*)&g_filled;
    sh_par[2]=*(volatile float*)&g_sbar;
  }
  __syncthreads();
  const float alpha  = sh_par[0];
  const float filled = sh_par[1];
  const float sbar   = sh_par[2];

  #pragma unroll
  for (int j=0;j<RPT;j++){
    int n = tid + j*NT;
    float x = sh_s[n];
    if (x == ninf) sh_s[n] = filled;
  }
  // precompute Q matrices + chi init
  float h0=0.f, h1=0.f, oldc=0.f;
  if (tid < KP1){
    float a   = (float)tid;
    float lam = 2.f*alpha*a;
    float q = 1.f;
    sh_Qr[tid*QRS+0] = 1.f;
    sh_Qc[0*QCS+tid] = 1.f;
    #pragma unroll
    for (int d=1; d<DD; d++){
      q = q * lam / (float)d;
      sh_Qr[tid*QRS+d] = q;
      sh_Qc[d*QCS+tid] = q;
    }
    float da = a - sbar;
    float c = __expf(-alpha*da*da) * (1.f/(float)KP1);   // chi init
    sh_chi[tid] = c;
    h0 = c; h1 = c; oldc = c;
  }
  if (tid == 0){ sh_conv[0]=0; sh_conv[1]=0; }
  __syncthreads();

  // ds = s - sbar, packed
  u64 ds2[4];
  #pragma unroll
  for (int q=0;q<4;q++){
    float da = sh_s[tid + (2*q  )*NT] - sbar;
    float db = sh_s[tid + (2*q+1)*NT] - sbar;
    ds2[q] = pack2(da, db);
  }
  u64 y2[4];

  // ===== Sinkhorn loop (Taylor-compressed) =====
  #pragma unroll 1
  for (int it=0; it<MAXIT; ++it){
    // step1: C_d = sum_a chi_a * Q[d][a]   (14 threads)
    if (tid < DD){
      const float* qc = &sh_Qc[tid*QCS];
      float c0=0.f,c1=0.f,c2=0.f,c3=0.f;
      #pragma unroll
      for (int a=0; a<64; a+=4){
        c0 += sh_chi[a  ]*qc[a  ];
        c1 += sh_chi[a+1]*qc[a+1];
        c2 += sh_chi[a+2]*qc[a+2];
        c3 += sh_chi[a+3]*qc[a+3];
      }
      sh_C[tid] = ((c0+c1)+(c2+c3)) + sh_chi[64]*qc[64];
    }
    __syncthreads();
    // step2: acc = poly(C, ds), y = MU/acc
    {
      float cT = sh_C[DD-1];
      u64 a0=pack2(cT,cT), a1=a0, a2=a0, a3=a0;
      #pragma unroll
      for (int d=DD-2; d>=0; --d){
        float c = sh_C[d];
        u64 f = pack2(c,c);
        a0=fma2(a0,ds2[0],f); a1=fma2(a1,ds2[1],f); a2=fma2(a2,ds2[2],f); a3=fma2(a3,ds2[3],f);
      }
      float lo,hi;
      unpack2(a0,lo,hi); y2[0]=pack2(__fdividef(MU_F,lo), __fdividef(MU_F,hi));
      unpack2(a1,lo,hi); y2[1]=pack2(__fdividef(MU_F,lo), __fdividef(MU_F,hi));
      unpack2(a2,lo,hi); y2[2]=pack2(__fdividef(MU_F,lo), __fdividef(MU_F,hi));
      unpack2(a3,lo,hi); y2[3]=pack2(__fdividef(MU_F,lo), __fdividef(MU_F,hi));
    }
    // step3: T-partials: T_d = sum_n y * ds^d  (64 partials per d)
    {
      u64 t0=y2[0], t1=y2[1], t2=y2[2], t3=y2[3];
      #pragma unroll
      for (int d=0; d<DD; d++){
        u64 p = add2(add2(t0,t1), add2(t2,t3));
        float lo,hi; unpack2(p,lo,hi);
        float mv = lo + hi;
        mv += __shfl_xor_sync(0xffffffffu, mv, 16);
        mv += __shfl_xor_sync(0xffffffffu, mv, 8);
        if (lane < 8) sh_red[d*TSTR + wid*8 + lane] = mv;
        if (d < DD-1){
          t0=mul2(t0,ds2[0]); t1=mul2(t1,ds2[1]); t2=mul2(t2,ds2[2]); t3=mul2(t3,ds2[3]);
        }
      }
    }
    __syncthreads();
    // owner region on warps 0-2 (threads 0-95); others go straight to the full barrier
    if (tid < 96){
      if (tid < DD){                       // step4: T_d final (64 adds)
        const float4* r4 = (const float4*)&sh_red[tid*TSTR];
        float s0=0.f,s1=0.f,s2=0.f,s3=0.f;
        #pragma unroll
        for (int p=0;p<16;p+=4){
          float4 v0=r4[p], v1=r4[p+1], v2=r4[p+2], v3=r4[p+3];
          s0 += (v0.x+v0.y)+(v0.z+v0.w);
          s1 += (v1.x+v1.y)+(v1.z+v1.w);
          s2 += (v2.x+v2.y)+(v2.z+v2.w);
          s3 += (v3.x+v3.y)+(v3.z+v3.w);
        }
        sh_T[tid] = (s0+s1)+(s2+s3);
      }
      asm volatile("bar.sync 1, 96;" ::: "memory");
      if (tid < KP1){                      // step5: S_a, chi update, Steffensen
        const float* qr = &sh_Qr[tid*QRS];
        float S = 0.f;
        #pragma unroll
        for (int d=0; d<DD; d++) S += qr[d]*sh_T[d];
        float nuv = (tid==0) ? ((float)(NN-KK)/(float)NN) : MU_F;
        float newc = __fdividef(nuv, S);
        if (fabsf(newc - oldc) > CONV_TOL*fabsf(oldc)) sh_conv[it&1] = 1;
        float store = newc;
        if ((it & 1) == 0){
          h1 = newc;
        } else {
          float d1 = h1 - h0, d2 = newc - h1;
          float den = d2 - d1;
          if (fabsf(den) > 1e-30f){
            float ext = newc - (d2*d2)/den;
            if (ext > 0.f && isfinite(ext)) store = ext;
          }
          h0 = store;
        }
        sh_chi[tid] = store;
        oldc = store;
        if (tid == 0) sh_conv[(it+1)&1] = 0;
      }
    }
    __syncthreads();
    if (sh_conv[it&1] == 0) break;
  }

  // w~ = exp(2*alpha*ds) for the final Gamma pass
  u64 w2[4];
  #pragma unroll
  for (int q=0;q<4;q++){
    float lo,hi; unpack2(ds2[q],lo,hi);
    w2[q] = pack2(__expf(2.f*alpha*lo), __expf(2.f*alpha*hi));
  }

  // ===== hybrid bitonic sort: 8 consecutive elems per thread =====
  float sv[8];
  const int base8 = tid*8;
  {
    float4 p0 = *(const float4*)&sh_s[base8];
    float4 p1 = *(const float4*)&sh_s[base8+4];
    sv[0]=p0.x; sv[1]=p0.y; sv[2]=p0.z; sv[3]=p0.w;
    sv[4]=p1.x; sv[5]=p1.y; sv[6]=p1.z; sv[7]=p1.w;
  }
  for (int kk2=2; kk2<=NN; kk2<<=1){
    for (int jj=kk2>>1; jj>=256; jj>>=1){
      *(float4*)&sh_red[base8]   = make_float4(sv[0],sv[1],sv[2],sv[3]);
      *(float4*)&sh_red[base8+4] = make_float4(sv[4],sv[5],sv[6],sv[7]);
      __syncthreads();
      int delta = jj>>3;
      int pc = tid ^ delta;
      bool tmin = (((base8 & kk2)==0) == ((tid & delta)==0));
      float4 q0 = *(const float4*)&sh_red[pc*8];
      float4 q1 = *(const float4*)&sh_red[pc*8+4];
      float o[8] = {q0.x,q0.y,q0.z,q0.w,q1.x,q1.y,q1.z,q1.w};
      #pragma unroll
      for (int m=0;m<8;m++) sv[m] = tmin ? fminf(sv[m],o[m]) : fmaxf(sv[m],o[m]);
      __syncthreads();
    }
    {
      int jj0 = (kk2>>1) > 128 ? 128 : (kk2>>1);
      for (int jj=jj0; jj>=8; jj>>=1){
        int delta = jj>>3;
        bool tmin = (((base8 & kk2)==0) == ((tid & delta)==0));
        #pragma unroll
        for (int m=0;m<8;m++){
          float o = __shfl_xor_sync(0xffffffffu, sv[m], delta);
          sv[m] = tmin ? fminf(sv[m],o) : fmaxf(sv[m],o);
        }
      }
    }
    {
      int jj0 = (kk2>>1) > 4 ? 4 : (kk2>>1);
      for (int jj=jj0; jj>=1; jj>>=1){
        #pragma unroll
        for (int m=0;m<8;m++){
          if ((m & jj)==0){
            int m2 = m | jj;
            bool asc = (((base8+m) & kk2)==0);
            float a=sv[m], bb=sv[m2];
            if ((a>bb)==asc){ sv[m]=bb; sv[m2]=a; }
          }
        }
      }
    }
  }

  // ===== tau + top-K =====
  {
    float4 w0 = *(const float4*)&W[base8];
    float4 w1 = *(const float4*)&W[base8+4];
    float part = sv[0]*w0.x + sv[1]*w0.y + sv[2]*w0.z + sv[3]*w0.w
               + sv[4]*w1.x + sv[5]*w1.y + sv[6]*w1.z + sv[7]*w1.w;
    #pragma unroll
    for (int o=16;o>0;o>>=1) part += __shfl_xor_sync(0xffffffffu, part, o);
    if (lane==0) sh_wred[wid] = part;
    if (tid >= NT-8){
      #pragma unroll
      for (int m=0;m<8;m++) sh_tk[NN-1-base8-m] = sv[m];
    }
    __syncthreads();
    if (tid==0){
      float tau=0.f;
      #pragma unroll
      for (int q=0;q<NWARP;q++) tau += sh_wred[q];
      sh_scalar[0] = 0.5f/tau;
    }
    __syncthreads();
  }
  const float hTau = sh_scalar[0];

  // ===== Gamma0 column sums Z_k =====
  #pragma unroll 1
  for (int c=0;c<4;c++){
    float z[16];
    #pragma unroll
    for (int q=0;q<16;q++) z[q]=0.f;
    #pragma unroll
    for (int j=0;j<RPT;j++){
      float s = sh_s[tid+j*NT];
      #pragma unroll
      for (int q=0;q<16;q++){
        float d = fabsf(sh_tk[c*16+q]-s);
        z[q] += fmaf(-0.5f, tanhA(d*hTau), 0.5f);
      }
    }
    #pragma unroll
    for (int q=0;q<16;q++){
      float mv = z[q];
      #pragma unroll
      for (int o=16;o>0;o>>=1) mv += __shfl_xor_sync(0xffffffffu, mv, o);
      if (lane==0) sh_red[q*NWARP + wid] = mv;
    }
    __syncthreads();
    if (tid < 16){
      float Z=0.f;
      #pragma unroll
      for (int q=0;q<NWARP;q++) Z += sh_red[tid*NWARP+q];
      sh_invZn[c*16+tid] = __fdividef(1.f, Z*(float)NN);
    }
    __syncthreads();
  }

  // packed per-pair tables: pair i covers anchors (lo=2i+2 -> k=62-2i, hi=2i+1 -> k=63-2i)
  if (tid < KK/2){
    sh_cp [tid] = pack2(sh_chi[2*tid+2], sh_chi[2*tid+1]);
    sh_izp[tid] = pack2(sh_invZn[62-2*tid], sh_invZn[63-2*tid]);
  }
  __syncthreads();

  // ===== final: Gamma, A, ||Gamma-Gamma0||^2 (paired f32x2) =====
  const u64 NN2 = pack2(2048.f, 2048.f);
  const u64 MH2 = pack2(-0.5f, -0.5f);
  const u64 PH2 = pack2( 0.5f,  0.5f);
  const u64 M12 = pack2(-1.f, -1.f);
  const float coef0 = sh_chi[0];
  float nrm = 0.f;
  u64 nrm2 = pack2(0.f, 0.f);
  #pragma unroll 1
  for (int j=0;j<RPT;j++){
    int n = tid + j*NT;
    float s = sh_s[n];
    float yj, wj;
    { float lo,hi;
      unpack2(y2[j>>1], lo, hi); yj = (j&1)?hi:lo;
      unpack2(w2[j>>1], lo, hi); wj = (j&1)?hi:lo; }
    float* orow = out + ((size_t)b*NN + n)*KK;
    float gam64 = yj * coef0;
    float ww = wj*wj;
    u64 ww2 = pack2(ww, ww);
    float t1v = yj*wj;
    u64 G2 = pack2(t1v*wj, t1v);
    u64 rs2 = pack2(0.f, 0.f);
    #pragma unroll 4
    for (int g=0; g<16; ++g){
      int kb = 60 - 4*g;
      u64 gamP = mul2(G2, sh_cp[2*g]);   G2 = mul2(G2, ww2);
      u64 gamQ = mul2(G2, sh_cp[2*g+1]); G2 = mul2(G2, ww2);
      float thP0 = tanhA(fabsf(sh_tk[kb+2]-s)*hTau);
      float thP1 = tanhA(fabsf(sh_tk[kb+3]-s)*hTau);
      float thQ0 = tanhA(fabsf(sh_tk[kb  ]-s)*hTau);
      float thQ1 = tanhA(fabsf(sh_tk[kb+1]-s)*hTau);
      u64 sgP = fma2(pack2(thP0,thP1), MH2, PH2);
      u64 sgQ = fma2(pack2(thQ0,thQ1), MH2, PH2);
      u64 g0P = mul2(sgP, sh_izp[2*g]);
      u64 g0Q = mul2(sgQ, sh_izp[2*g+1]);
      rs2 = add2(rs2, add2(g0P, g0Q));
      u64 dP = fma2(g0P, M12, gamP);
      u64 dQ = fma2(g0Q, M12, gamQ);
      nrm2 = fma2(dP, dP, nrm2);
      nrm2 = fma2(dQ, dQ, nrm2);
      float ql,qh,pl,ph;
      unpack2(mul2(gamQ, NN2), ql, qh);
      unpack2(mul2(gamP, NN2), pl, ph);
      *(float4*)(orow + kb) = make_float4(ql, qh, pl, ph);
    }
    float rl,rh; unpack2(rs2, rl, rh);
    float last = MU_F - (rl + rh);
    last = fminf(fmaxf(last, 1e-20f), 1.f-1e-20f);
    float dl = gam64 - last;
    nrm = fmaf(dl, dl, nrm);
  }
  { float nl,nh; unpack2(nrm2, nl, nh); nrm += nl + nh; }
  #pragma unroll
  for (int o=16;o>0;o>>=1) nrm += __shfl_xor_sync(0xffffffffu, nrm, o);
  if (lane==0) sh_wred[wid] = nrm;
  __syncthreads();
  if (tid==0){
    float sA=0.f;
    #pragma unroll
    for (int q=0;q<NWARP;q++) sA += sh_wred[q];
    g_normPart[b] = sA;
  }

  // ===== final norm via last-CTA ticket (self-resetting globals) =====
  if (tid==0){
    __threadfence();
    sh_last = (atomicAdd(&g_t2,1) == BSZ-1) ? 1 : 0;
  }
  __syncthreads();
  if (sh_last){
    __threadfence();
    float v = *(volatile float*)&g_normPart[tid];
    #pragma unroll
    for (int o=16;o>0;o>>=1) v += __shfl_xor_sync(0xffffffffu, v, o);
    if (lane==0) sh_wred[wid] = v;
    __syncthreads();
    if (tid==0){
      float sT=0.f;
      #pragma unroll
      for (int q=0;q<NWARP;q++) sT += sh_wred[q];
      out[(size_t)BSZ*NN*KK] = sqrtf(sT);
      g_t1=0; g_t2=0;
      g_maxEnc=0u; g_minEnc=0xffffffffu; g_anyMask=0;
      __threadfence();
      *(volatile int*)&g_phase = 0;
    }
  }
}

extern "C" void kernel_launch(void* const* d_in, const int* in_sizes, int n_in,
                              void* d_out, int out_size)
{
  const float* scores = (const float*)d_in[0];
  const float* W      = (const float*)d_in[1];
  if (n_in >= 2 && in_sizes[0] == NN && in_sizes[1] == BSZ*NN){
    const float* tmp = scores; scores = W; W = tmp;
  }
  float* out = (float*)d_out;
  (void)out_size;

  k_all<<<BSZ, NT>>>(scores, W, out);
}